// round 2
// baseline (speedup 1.0000x reference)
#include <cuda_runtime.h>

#define N_FFT   2048
#define HALF_N  1024
#define L_SIG   1024
#define H_DIM   512
#define THREADS 256
#define LOG2N   11

// Scratch: k spectrum (512 x 2048 complex) and twiddle table w_r = exp(-2*pi*i*r/2048)
__device__ float2 g_kf[H_DIM * N_FFT];   // 8 MB
__device__ float2 g_tw[HALF_N];          // 8 KB

__global__ void init_twiddle_kernel() {
    int r = blockIdx.x * blockDim.x + threadIdx.x;
    if (r < HALF_N) {
        float s, c;
        // exp(-2*pi*i*r/2048) = cos(-pi*r/1024) + i*sin(-pi*r/1024)
        sincospif(-(float)r / 1024.0f, &s, &c);
        g_tw[r] = make_float2(c, s);
    }
}

// Stockham radix-2 DIT, N=2048, 256 threads, ping-pong smem buffers.
// If ZPAD, the logical upper half (indices 1024..2047) of the input is zero and
// is NEVER read or written before stage 0; stage 0 degenerates to a duplicate.
// Returns pointer to the buffer holding the result.
template <bool ZPAD>
__device__ __forceinline__ float2* fft2048(float2* x, float2* y,
                                           const float2* __restrict__ tw, int tid) {
    __syncthreads();
    if (ZPAD) {
        // stage 0 with b == 0:  y[2t] = y[2t+1] = x[t]
        #pragma unroll
        for (int i = 0; i < 4; i++) {
            int t = tid + i * THREADS;
            float2 a = x[t];
            y[2 * t]     = a;
            y[2 * t + 1] = a;
        }
        float2* tmp = x; x = y; y = tmp;
    }
    #pragma unroll
    for (int s = (ZPAD ? 1 : 0); s < LOG2N; s++) {
        const int Ls = 1 << s;
        __syncthreads();
        #pragma unroll
        for (int i = 0; i < 4; i++) {
            int t = tid + i * THREADS;        // 0..1023
            int k = t & (Ls - 1);
            float2 a = x[t];
            float2 b = x[t + HALF_N];
            float2 w = tw[k << (10 - s)];     // exp(-pi*i*k/Ls)
            float2 wb = make_float2(w.x * b.x - w.y * b.y,
                                    w.x * b.y + w.y * b.x);
            int i0 = 2 * t - k;               // = 2*(t-k) + k
            y[i0]      = make_float2(a.x + wb.x, a.y + wb.y);
            y[i0 + Ls] = make_float2(a.x - wb.x, a.y - wb.y);
        }
        float2* tmp = x; x = y; y = tmp;
    }
    __syncthreads();
    return x;
}

// One block per h: FFT of zero-padded real k row -> g_kf[h]
__global__ void __launch_bounds__(THREADS) kf_kernel(const float* __restrict__ k) {
    __shared__ float2 bufA[N_FFT];
    __shared__ float2 bufB[N_FFT];
    __shared__ float2 tws[HALF_N];
    const int h = blockIdx.x;
    const int tid = threadIdx.x;
    const float* kr = k + (size_t)h * L_SIG;
    #pragma unroll
    for (int i = 0; i < 4; i++) {
        int idx = tid + i * THREADS;
        bufA[idx] = make_float2(kr[idx], 0.0f);   // upper half implicit zero (ZPAD)
    }
    #pragma unroll
    for (int i = tid; i < HALF_N; i += THREADS) tws[i] = g_tw[i];

    float2* res = fft2048<true>(bufA, bufB, tws, tid);

    float2* dst = g_kf + (size_t)h * N_FFT;
    #pragma unroll
    for (int i = 0; i < 8; i++) {
        int idx = tid + i * THREADS;
        dst[idx] = res[idx];
    }
}

// One block per (h, batch-pair). Real-packing trick: z = u_b + i*u_{b+1};
// since k is real and conv is linear, IFFT(FFT(z)*K) = y_b + i*y_{b+1}.
// IFFT(v) = conj(FFT(conj(v)))/N, so we FFT conj(z_f*K) and read Re / -Im.
__global__ void __launch_bounds__(THREADS) conv_kernel(const float* __restrict__ u,
                                                       const float* __restrict__ D,
                                                       float* __restrict__ out) {
    __shared__ float2 bufA[N_FFT];
    __shared__ float2 bufB[N_FFT];
    __shared__ float2 tws[HALF_N];
    const int h   = blockIdx.x;   // 0..511
    const int bp  = blockIdx.y;   // 0..7  (pair of batches 2*bp, 2*bp+1)
    const int tid = threadIdx.x;

    const size_t row_stride = (size_t)H_DIM * L_SIG;      // stride between b indices
    const float* u0 = u + ((size_t)(2 * bp) * H_DIM + h) * L_SIG;
    const float* u1 = u0 + row_stride;

    float ur0[4], ur1[4];
    #pragma unroll
    for (int i = 0; i < 4; i++) {
        int idx = tid + i * THREADS;
        ur0[i] = u0[idx];
        ur1[i] = u1[idx];
        bufA[idx] = make_float2(ur0[i], ur1[i]);   // upper half implicit zero (ZPAD)
    }
    #pragma unroll
    for (int i = tid; i < HALF_N; i += THREADS) tws[i] = g_tw[i];

    float2* res = fft2048<true>(bufA, bufB, tws, tid);

    // pointwise: res = conj(res * K_h)
    const float2* __restrict__ kf = g_kf + (size_t)h * N_FFT;
    #pragma unroll
    for (int i = 0; i < 8; i++) {
        int idx = tid + i * THREADS;
        float2 z = res[idx];
        float2 K = kf[idx];
        float re = z.x * K.x - z.y * K.y;
        float im = z.x * K.y + z.y * K.x;
        res[idx] = make_float2(re, -im);
    }

    float2* other = (res == bufA) ? bufB : bufA;
    float2* res2 = fft2048<false>(res, other, tws, tid);

    const float d   = D[h];
    const float inv = 1.0f / (float)N_FFT;
    float* y0 = out + ((size_t)(2 * bp) * H_DIM + h) * L_SIG;
    float* y1 = y0 + row_stride;
    #pragma unroll
    for (int i = 0; i < 4; i++) {
        int idx = tid + i * THREADS;
        float2 r = res2[idx];
        y0[idx] =  r.x * inv + ur0[i] * d;   // Re(ifft) -> batch 2*bp
        y1[idx] = -r.y * inv + ur1[i] * d;   // Im(ifft) -> batch 2*bp+1
    }
}

extern "C" void kernel_launch(void* const* d_in, const int* in_sizes, int n_in,
                              void* d_out, int out_size) {
    // metadata order: u (B,H,L) f32, k (H,L) f32, D (H,) f32, mat_2/4/8/16 (ignored:
    // they are exact DFT matrices broadcast over H; our twiddles reproduce them)
    const float* u = (const float*)d_in[0];
    const float* k = (const float*)d_in[1];
    const float* D = (const float*)d_in[2];
    float* out = (float*)d_out;

    init_twiddle_kernel<<<(HALF_N + 255) / 256, 256>>>();
    kf_kernel<<<H_DIM, THREADS>>>(k);
    conv_kernel<<<dim3(H_DIM, 8), THREADS>>>(u, D, out);
}

// round 3
// speedup vs baseline: 2.5600x; 2.5600x over previous
#include <cuda_runtime.h>

#define N_FFT   2048
#define L_SIG   1024
#define H_DIM   512
#define THREADS 256

// conflict-avoidance padding: one extra float2 per 32
#define PAD(i) ((i) + ((i) >> 5))
#define BUF_ELEMS (N_FFT + (N_FFT >> 5))   // 2112

__device__ float2 g_kf[H_DIM * N_FFT];   // 8 MB k-spectrum scratch

__device__ __forceinline__ float2 cadd(float2 a, float2 b){ return make_float2(a.x+b.x, a.y+b.y); }
__device__ __forceinline__ float2 csub(float2 a, float2 b){ return make_float2(a.x-b.x, a.y-b.y); }
__device__ __forceinline__ float2 cmul(float2 a, float2 b){
    return make_float2(a.x*b.x - a.y*b.y, a.x*b.y + a.y*b.x);
}
__device__ __forceinline__ float2 mul_negi(float2 a){ return make_float2(a.y, -a.x); } // a * (-i)

__device__ __forceinline__ void dft4(float2& x0, float2& x1, float2& x2, float2& x3){
    float2 t0 = cadd(x0,x2), t1 = csub(x0,x2);
    float2 t2 = cadd(x1,x3), t3 = csub(x1,x3);
    float2 it3 = mul_negi(t3);
    x0 = cadd(t0,t2);
    x1 = cadd(t1,it3);
    x2 = csub(t0,t2);
    x3 = csub(t1,it3);
}

// 8-point DFT, natural order in/out
__device__ __forceinline__ void dft8(float2 v[8]){
    const float c = 0.70710678118654752440f;
    float2 e0=v[0], e1=v[2], e2=v[4], e3=v[6];
    float2 o0=v[1], o1=v[3], o2=v[5], o3=v[7];
    dft4(e0,e1,e2,e3);
    dft4(o0,o1,o2,o3);
    float2 w1o = make_float2(c*(o1.x + o1.y), c*(o1.y - o1.x));   // o1 * W8^1
    float2 w2o = mul_negi(o2);                                    // o2 * W8^2
    float2 w3o = make_float2(c*(o3.y - o3.x), -c*(o3.x + o3.y));  // o3 * W8^3
    v[0]=cadd(e0,o0);  v[4]=csub(e0,o0);
    v[1]=cadd(e1,w1o); v[5]=csub(e1,w1o);
    v[2]=cadd(e2,w2o); v[6]=csub(e2,w2o);
    v[3]=cadd(e3,w3o); v[7]=csub(e3,w3o);
}

// 8-point DFT where v[4..7] are known zero (zero-padded input)
__device__ __forceinline__ void dft8_zp(float2 v[8]){
    const float c = 0.70710678118654752440f;
    float2 a0=v[0], a1=v[2], b0=v[1], b1=v[3];
    // E = DFT4(a0,a1,0,0), O = DFT4(b0,b1,0,0)
    float2 e0=cadd(a0,a1);
    float2 e1=make_float2(a0.x + a1.y, a0.y - a1.x);  // a0 - i a1
    float2 e2=csub(a0,a1);
    float2 e3=make_float2(a0.x - a1.y, a0.y + a1.x);  // a0 + i a1
    float2 q0=cadd(b0,b1);
    float2 q1=make_float2(b0.x + b1.y, b0.y - b1.x);
    float2 q2=csub(b0,b1);
    float2 q3=make_float2(b0.x - b1.y, b0.y + b1.x);
    float2 w1o = make_float2(c*(q1.x + q1.y), c*(q1.y - q1.x));
    float2 w2o = mul_negi(q2);
    float2 w3o = make_float2(c*(q3.y - q3.x), -c*(q3.x + q3.y));
    v[0]=cadd(e0,q0);  v[4]=csub(e0,q0);
    v[1]=cadd(e1,w1o); v[5]=csub(e1,w1o);
    v[2]=cadd(e2,w2o); v[6]=csub(e2,w2o);
    v[3]=cadd(e3,w3o); v[7]=csub(e3,w3o);
}

__device__ __forceinline__ void twiddle8(float2 v[8], float2 w1){
    float2 w = w1;
    v[1] = cmul(v[1], w);
    #pragma unroll
    for (int r = 2; r < 8; r++){ w = cmul(w, w1); v[r] = cmul(v[r], w); }
}

// 2048-pt FFT, radix 8*8*8*4 Stockham. Pass-1 input arrives in v[] (registers):
// v[r] corresponds to logical index tid + 256*r. Result left in buf (natural
// order, PAD-indexed), after a trailing __syncthreads.
template<bool ZPAD>
__device__ __forceinline__ void fft_passes(float2* buf, float2 v[8], int tid){
    const float TWO_PI = 6.28318530717958647693f;
    // ---- pass 1: R=8, L=1 (k=0 -> no twiddles)
    if (ZPAD) dft8_zp(v); else dft8(v);
    #pragma unroll
    for (int j = 0; j < 8; j++) buf[PAD(8*tid + j)] = v[j];
    __syncthreads();
    // ---- pass 2: R=8, L=8
    {
        #pragma unroll
        for (int r = 0; r < 8; r++) v[r] = buf[PAD(tid + (r<<8))];
        __syncthreads();
        int k = tid & 7;
        float s, c; __sincosf(-(float)k * (TWO_PI/64.f), &s, &c);
        twiddle8(v, make_float2(c, s));
        dft8(v);
        int base = ((tid >> 3) << 6) + k;
        #pragma unroll
        for (int j = 0; j < 8; j++) buf[PAD(base + (j<<3))] = v[j];
        __syncthreads();
    }
    // ---- pass 3: R=8, L=64
    {
        #pragma unroll
        for (int r = 0; r < 8; r++) v[r] = buf[PAD(tid + (r<<8))];
        __syncthreads();
        int k = tid & 63;
        float s, c; __sincosf(-(float)k * (TWO_PI/512.f), &s, &c);
        twiddle8(v, make_float2(c, s));
        dft8(v);
        int base = ((tid >> 6) << 9) + k;
        #pragma unroll
        for (int j = 0; j < 8; j++) buf[PAD(base + (j<<6))] = v[j];
        __syncthreads();
    }
    // ---- pass 4: R=4, L=512 (two butterflies per thread: t0=tid, t1=tid+256)
    {
        #pragma unroll
        for (int r = 0; r < 4; r++) v[r]     = buf[PAD(tid       + (r<<9))];
        #pragma unroll
        for (int r = 0; r < 4; r++) v[4 + r] = buf[PAD(tid + 256 + (r<<9))];
        __syncthreads();
        float s, c;
        __sincosf(-(float)tid * (TWO_PI/2048.f), &s, &c);
        float2 w1 = make_float2(c, s);
        float2 w2 = cmul(w1, w1), w3 = cmul(w2, w1);
        v[1]=cmul(v[1],w1); v[2]=cmul(v[2],w2); v[3]=cmul(v[3],w3);
        dft4(v[0], v[1], v[2], v[3]);
        int t1 = tid + 256;
        __sincosf(-(float)t1 * (TWO_PI/2048.f), &s, &c);
        float2 u1 = make_float2(c, s);
        float2 u2 = cmul(u1, u1), u3 = cmul(u2, u1);
        v[5]=cmul(v[5],u1); v[6]=cmul(v[6],u2); v[7]=cmul(v[7],u3);
        dft4(v[4], v[5], v[6], v[7]);
        #pragma unroll
        for (int j = 0; j < 4; j++) buf[PAD(tid + (j<<9))] = v[j];
        #pragma unroll
        for (int j = 0; j < 4; j++) buf[PAD(t1  + (j<<9))] = v[4 + j];
        __syncthreads();
    }
}

// One block per h: spectrum of zero-padded k row -> g_kf[h]
__global__ void __launch_bounds__(THREADS) kf_kernel(const float* __restrict__ k) {
    __shared__ float2 buf[BUF_ELEMS];
    const int h = blockIdx.x;
    const int tid = threadIdx.x;
    const float* kr = k + (size_t)h * L_SIG;
    float2 v[8];
    #pragma unroll
    for (int i = 0; i < 4; i++) v[i] = make_float2(kr[tid + (i<<8)], 0.0f);

    fft_passes<true>(buf, v, tid);

    float2* dst = g_kf + (size_t)h * N_FFT;
    #pragma unroll
    for (int r = 0; r < 8; r++) {
        int idx = tid + (r<<8);
        dst[idx] = buf[PAD(idx)];
    }
}

// One block per (h, batch-pair). z = u_b + i*u_{b+1}; IFFT(FFT(z)*K) = y_b + i*y_{b+1}
// (k real). IFFT(v) = conj(FFT(conj(v)))/N: we FFT conj(z_f*K) and read Re / -Im.
__global__ void __launch_bounds__(THREADS) conv_kernel(const float* __restrict__ u,
                                                       const float* __restrict__ D,
                                                       float* __restrict__ out) {
    __shared__ float2 buf[BUF_ELEMS];
    const int h   = blockIdx.x;   // 0..511
    const int bp  = blockIdx.y;   // 0..7
    const int tid = threadIdx.x;

    const size_t row_stride = (size_t)H_DIM * L_SIG;
    const float* u0 = u + ((size_t)(2 * bp) * H_DIM + h) * L_SIG;
    const float* u1 = u0 + row_stride;

    float2 v[8];
    float ur0[4], ur1[4];
    #pragma unroll
    for (int i = 0; i < 4; i++) {
        int idx = tid + (i<<8);
        ur0[i] = u0[idx];
        ur1[i] = u1[idx];
        v[i] = make_float2(ur0[i], ur1[i]);
    }

    fft_passes<true>(buf, v, tid);

    // pointwise: v = conj(Z * K), feeding pass-1 of the second FFT directly
    const float2* __restrict__ kf = g_kf + (size_t)h * N_FFT;
    #pragma unroll
    for (int r = 0; r < 8; r++) {
        int idx = tid + (r<<8);
        float2 z = buf[PAD(idx)];
        float2 K = kf[idx];
        v[r] = make_float2(z.x*K.x - z.y*K.y, -(z.x*K.y + z.y*K.x));
    }
    __syncthreads();   // everyone done reading buf before pass-1 writes

    fft_passes<false>(buf, v, tid);

    const float d   = D[h];
    const float inv = 1.0f / (float)N_FFT;
    float* y0 = out + ((size_t)(2 * bp) * H_DIM + h) * L_SIG;
    float* y1 = y0 + row_stride;
    #pragma unroll
    for (int i = 0; i < 4; i++) {
        int idx = tid + (i<<8);
        float2 r = buf[PAD(idx)];
        y0[idx] =  r.x * inv + ur0[i] * d;
        y1[idx] = -r.y * inv + ur1[i] * d;
    }
}

extern "C" void kernel_launch(void* const* d_in, const int* in_sizes, int n_in,
                              void* d_out, int out_size) {
    const float* u = (const float*)d_in[0];
    const float* k = (const float*)d_in[1];
    const float* D = (const float*)d_in[2];
    float* out = (float*)d_out;

    kf_kernel<<<H_DIM, THREADS>>>(k);
    conv_kernel<<<dim3(H_DIM, 8), THREADS>>>(u, D, out);
}

// round 5
// speedup vs baseline: 3.8202x; 1.4923x over previous
#include <cuda_runtime.h>

#define N_FFT   2048
#define L_SIG   1024
#define H_DIM   512
#define THREADS 128

// bank-conflict padding: one extra float2 per 16
#define PAD(i) ((i) + ((i) >> 4))
#define BUF_ELEMS (N_FFT + (N_FFT >> 4))   // 2176 float2 = 17.4 KB

__device__ float2 g_kf[H_DIM * N_FFT];   // 8 MB k-spectrum scratch

__device__ __forceinline__ float2 cadd(float2 a, float2 b){ return make_float2(a.x+b.x, a.y+b.y); }
__device__ __forceinline__ float2 csub(float2 a, float2 b){ return make_float2(a.x-b.x, a.y-b.y); }
__device__ __forceinline__ float2 cmul(float2 a, float2 b){
    return make_float2(a.x*b.x - a.y*b.y, a.x*b.y + a.y*b.x);
}
__device__ __forceinline__ float2 mul_negi(float2 a){ return make_float2(a.y, -a.x); } // a * (-i)

__device__ __forceinline__ void dft4(float2& x0, float2& x1, float2& x2, float2& x3){
    float2 t0 = cadd(x0,x2), t1 = csub(x0,x2);
    float2 t2 = cadd(x1,x3), t3 = csub(x1,x3);
    float2 it3 = mul_negi(t3);
    x0 = cadd(t0,t2);
    x1 = cadd(t1,it3);
    x2 = csub(t0,t2);
    x3 = csub(t1,it3);
}

// 8-point DFT, natural order in/out
__device__ __forceinline__ void dft8(float2 v[8]){
    const float c = 0.70710678118654752440f;
    float2 e0=v[0], e1=v[2], e2=v[4], e3=v[6];
    float2 o0=v[1], o1=v[3], o2=v[5], o3=v[7];
    dft4(e0,e1,e2,e3);
    dft4(o0,o1,o2,o3);
    float2 w1o = make_float2(c*(o1.x + o1.y), c*(o1.y - o1.x));   // o1 * W8^1
    float2 w2o = mul_negi(o2);                                    // o2 * W8^2
    float2 w3o = make_float2(c*(o3.y - o3.x), -c*(o3.x + o3.y));  // o3 * W8^3
    v[0]=cadd(e0,o0);  v[4]=csub(e0,o0);
    v[1]=cadd(e1,w1o); v[5]=csub(e1,w1o);
    v[2]=cadd(e2,w2o); v[6]=csub(e2,w2o);
    v[3]=cadd(e3,w3o); v[7]=csub(e3,w3o);
}

// 8-point DFT computing only outputs p=0..3 (into v[0..3])
__device__ __forceinline__ void dft8_half(float2 v[8]){
    const float c = 0.70710678118654752440f;
    float2 e0=v[0], e1=v[2], e2=v[4], e3=v[6];
    float2 o0=v[1], o1=v[3], o2=v[5], o3=v[7];
    dft4(e0,e1,e2,e3);
    dft4(o0,o1,o2,o3);
    float2 w1o = make_float2(c*(o1.x + o1.y), c*(o1.y - o1.x));
    float2 w2o = mul_negi(o2);
    float2 w3o = make_float2(c*(o3.y - o3.x), -c*(o3.x + o3.y));
    v[0]=cadd(e0,o0);
    v[1]=cadd(e1,w1o);
    v[2]=cadd(e2,w2o);
    v[3]=cadd(e3,w3o);
}

// 16-point DFT as 4x4. Natural input in v[0..15].
// OUTPUT PERMUTED: X[q + 4r] ends up in slot v[4q + r]  (use SLOT16 when storing).
// If ZP, inputs v[8..15] are treated as zero (not read).
#define SLOT16(p) (4*((p)&3) + ((p)>>2))
template<bool ZP>
__device__ __forceinline__ void dft16(float2 v[16]){
    const float c1 = 0.92387953251128675613f; // cos(pi/8)
    const float s1 = 0.38268343236508977173f; // sin(pi/8)
    const float r2 = 0.70710678118654752440f;
    // stage 1: dft4 over stride-4 groups (b fixed). Result A_b[q] -> v[b+4q]
    #pragma unroll
    for (int b = 0; b < 4; b++){
        if (ZP) {
            float2 t0 = v[b], t1 = v[b+4];
            v[b]    = cadd(t0,t1);
            v[b+4]  = make_float2(t0.x + t1.y, t0.y - t1.x); // t0 - i*t1
            v[b+8]  = csub(t0,t1);
            v[b+12] = make_float2(t0.x - t1.y, t0.y + t1.x); // t0 + i*t1
        } else {
            dft4(v[b], v[b+4], v[b+8], v[b+12]);
        }
    }
    // twiddle W16^{b*q} on slot v[b+4q]
    v[5]  = cmul(v[5],  make_float2(c1, -s1));   // W16^1
    v[9]  = cmul(v[9],  make_float2(r2, -r2));   // W16^2
    v[13] = cmul(v[13], make_float2(s1, -c1));   // W16^3
    v[6]  = cmul(v[6],  make_float2(r2, -r2));   // W16^2
    v[10] = mul_negi(v[10]);                     // W16^4
    v[14] = cmul(v[14], make_float2(-r2, -r2));  // W16^6
    v[7]  = cmul(v[7],  make_float2(s1, -c1));   // W16^3
    v[11] = cmul(v[11], make_float2(-r2, -r2));  // W16^6
    v[15] = cmul(v[15], make_float2(-c1, s1));   // W16^9
    // stage 2: dft4 over b within each q block: slots 4q..4q+3
    #pragma unroll
    for (int q = 0; q < 4; q++)
        dft4(v[4*q], v[4*q+1], v[4*q+2], v[4*q+3]);
}

// 2048-pt FFT, radix 16*16*8 Stockham, 128 threads, 16 complex regs/thread.
// Input arrives in v[]: v[m] = x[tid + 128*m] (for ZPAD only m<8 used; rest zero).
// Result left in buf in natural order (PAD-indexed); trailing __syncthreads.
// If TRUNC, only outputs 0..1023 are computed/stored in the final pass.
template<bool ZPAD, bool TRUNC>
__device__ __forceinline__ void fft2048(float2* buf, float2 v[16], int tid){
    const float TWO_PI = 6.28318530717958647693f;
    // ---- pass A: R=16, L=1 (no twiddles)
    dft16<ZPAD>(v);
    {
        int base = tid << 4;
        #pragma unroll
        for (int p = 0; p < 16; p++)
            buf[PAD(base + p)] = v[SLOT16(p)];
    }
    __syncthreads();
    // ---- pass B: R=16, L=16
    {
        #pragma unroll
        for (int m = 0; m < 16; m++) v[m] = buf[PAD(tid + (m<<7))];
        __syncthreads();
        int k = tid & 15;
        float s, c; __sincosf(-(float)k * (TWO_PI/256.f), &s, &c);
        float2 w1 = make_float2(c, s), w = w1;
        v[1] = cmul(v[1], w);
        #pragma unroll
        for (int m = 2; m < 16; m++){ w = cmul(w, w1); v[m] = cmul(v[m], w); }
        dft16<false>(v);
        int base = ((tid >> 4) << 8) + k;
        #pragma unroll
        for (int p = 0; p < 16; p++)
            buf[PAD(base + (p<<4))] = v[SLOT16(p)];
    }
    __syncthreads();
    // ---- pass C: R=8, L=256, two butterflies per thread (t = tid, tid+128)
    {
        #pragma unroll
        for (int m = 0; m < 8; m++) v[m]     = buf[PAD(tid       + (m<<8))];
        #pragma unroll
        for (int m = 0; m < 8; m++) v[8 + m] = buf[PAD(tid + 128 + (m<<8))];
        __syncthreads();
        float s, c;
        __sincosf(-(float)tid * (TWO_PI/2048.f), &s, &c);
        float2 w1 = make_float2(c, s), w = w1;
        v[1] = cmul(v[1], w);
        #pragma unroll
        for (int m = 2; m < 8; m++){ w = cmul(w, w1); v[m] = cmul(v[m], w); }
        int t1 = tid + 128;
        __sincosf(-(float)t1 * (TWO_PI/2048.f), &s, &c);
        float2 u1 = make_float2(c, s); w = u1;
        v[9] = cmul(v[9], w);
        #pragma unroll
        for (int m = 2; m < 8; m++){ w = cmul(w, u1); v[8+m] = cmul(v[8+m], w); }
        if (TRUNC) {
            dft8_half(v);
            dft8_half(v + 8);
            #pragma unroll
            for (int p = 0; p < 4; p++) buf[PAD(tid       + (p<<8))] = v[p];
            #pragma unroll
            for (int p = 0; p < 4; p++) buf[PAD(tid + 128 + (p<<8))] = v[8+p];
        } else {
            dft8(v);
            dft8(v + 8);
            #pragma unroll
            for (int p = 0; p < 8; p++) buf[PAD(tid       + (p<<8))] = v[p];
            #pragma unroll
            for (int p = 0; p < 8; p++) buf[PAD(tid + 128 + (p<<8))] = v[8+p];
        }
    }
    __syncthreads();
}

// One block per h: spectrum of zero-padded k row -> g_kf[h]
__global__ void __launch_bounds__(THREADS, 4) kf_kernel(const float* __restrict__ k) {
    __shared__ float2 buf[BUF_ELEMS];
    const int h = blockIdx.x;
    const int tid = threadIdx.x;
    const float* kr = k + (size_t)h * L_SIG;
    float2 v[16];
    #pragma unroll
    for (int m = 0; m < 8; m++) v[m] = make_float2(kr[tid + (m<<7)], 0.0f);

    fft2048<true, false>(buf, v, tid);

    float2* dst = g_kf + (size_t)h * N_FFT;
    #pragma unroll
    for (int m = 0; m < 16; m++) {
        int idx = tid + (m<<7);
        dst[idx] = buf[PAD(idx)];
    }
}

// One block per (h, batch-pair). z = u_b + i*u_{b+1}; IFFT(FFT(z)*K) = y_b + i*y_{b+1}
// (k real). IFFT(v) = conj(FFT(conj(v)))/N: FFT conj(z_f*K), read Re / -Im.
__global__ void __launch_bounds__(THREADS, 4) conv_kernel(const float* __restrict__ u,
                                                          const float* __restrict__ D,
                                                          float* __restrict__ out) {
    __shared__ float2 buf[BUF_ELEMS];
    const int h   = blockIdx.x;   // 0..511
    const int bp  = blockIdx.y;   // 0..7
    const int tid = threadIdx.x;

    const size_t row_stride = (size_t)H_DIM * L_SIG;
    const float* u0 = u + ((size_t)(2 * bp) * H_DIM + h) * L_SIG;
    const float* u1 = u0 + row_stride;

    float2 v[16];
    #pragma unroll
    for (int m = 0; m < 8; m++) {
        int idx = tid + (m<<7);
        v[m] = make_float2(u0[idx], u1[idx]);
    }

    fft2048<true, false>(buf, v, tid);

    // pointwise: v = conj(Z * K), feeding pass-A of the inverse FFT directly
    const float2* __restrict__ kf = g_kf + (size_t)h * N_FFT;
    #pragma unroll
    for (int m = 0; m < 16; m++) {
        int idx = tid + (m<<7);
        float2 z = buf[PAD(idx)];
        float2 K = kf[idx];
        v[m] = make_float2(z.x*K.x - z.y*K.y, -(z.x*K.y + z.y*K.x));
    }
    __syncthreads();   // all reads of buf done before pass-A writes

    fft2048<false, true>(buf, v, tid);

    const float d   = D[h];
    const float inv = 1.0f / (float)N_FFT;
    float* y0 = out + ((size_t)(2 * bp) * H_DIM + h) * L_SIG;
    float* y1 = y0 + row_stride;
    #pragma unroll
    for (int i = 0; i < 8; i++) {
        int idx = tid + (i<<7);
        float2 r = buf[PAD(idx)];
        y0[idx] =  r.x * inv + u0[idx] * d;   // L2-hot reload of u
        y1[idx] = -r.y * inv + u1[idx] * d;
    }
}

extern "C" void kernel_launch(void* const* d_in, const int* in_sizes, int n_in,
                              void* d_out, int out_size) {
    const float* u = (const float*)d_in[0];
    const float* k = (const float*)d_in[1];
    const float* D = (const float*)d_in[2];
    float* out = (float*)d_out;

    kf_kernel<<<H_DIM, THREADS>>>(k);
    conv_kernel<<<dim3(H_DIM, 8), THREADS>>>(u, D, out);
}